// round 3
// baseline (speedup 1.0000x reference)
#include <cuda_runtime.h>
#include <cstdint>
#include <cstddef>

#define SEQ   512
#define BATCH 64
#define INDIM 128
#define HDIM  512

#define GB 8     // batch-tile blocks
#define GJ 16    // j-tile blocks  (GB*GJ = 128 blocks, all co-resident)
#define BT 8     // batch rows per block   (64/GB)
#define JT 32    // h columns per block    (512/GJ)
#define RTHREADS 256

typedef unsigned long long u64;

// step-ping-pong hidden state + per-block completion flags (device globals: no allocs)
__device__ float g_h[2][BATCH][HDIM];
__device__ int   g_flag[GB][GJ];

__device__ __forceinline__ int ld_acquire(const int* p) {
    int v;
    asm volatile("ld.global.acquire.gpu.s32 %0, [%1];" : "=r"(v) : "l"(p) : "memory");
    return v;
}
__device__ __forceinline__ void st_release(int* p, int v) {
    asm volatile("st.global.release.gpu.s32 [%0], %1;" :: "l"(p), "r"(v) : "memory");
}
__device__ __forceinline__ u64 fma2(u64 a, u64 b, u64 c) {
    u64 d;
    asm("fma.rn.f32x2 %0, %1, %2, %3;" : "=l"(d) : "l"(a), "l"(b), "l"(c));
    return d;
}

__global__ void reset_flags_kernel() {
    int t = threadIdx.x;
    if (t < GB * GJ) ((int*)g_flag)[t] = 0;
}

// ---------------------------------------------------------------------------
// xi kernel: out[s][b][h] = sum_k x[s][b][k] * Wi[h][k] + bi[h] + bh[h]
// (bh folded in here so the recurrent step is tanh(dot + xi')).
// ---------------------------------------------------------------------------
__global__ __launch_bounds__(256) void xi_kernel(
    const float* __restrict__ x, const float* __restrict__ Wi,
    const float* __restrict__ bi, const float* __restrict__ bh,
    float* __restrict__ out)
{
    extern __shared__ float sm[];
    float* ws = sm;               // [128][129]
    float* xs = sm + 128 * 129;   // [32][129]

    const int tid = threadIdx.x;
    const int sb0 = blockIdx.x * 32;
    const int h0  = blockIdx.y * 128;

    for (int i = tid; i < 128 * INDIM; i += 256) {
        int r = i >> 7, k = i & 127;
        ws[r * 129 + k] = Wi[(h0 + r) * INDIM + k];
    }
    for (int i = tid; i < 32 * INDIM; i += 256) {
        int r = i >> 7, k = i & 127;
        xs[r * 129 + k] = x[(size_t)(sb0 + r) * INDIM + k];
    }
    __syncthreads();

    const int ty = tid >> 5;
    const int tx = tid & 31;

    float acc[4][4];
#pragma unroll
    for (int i = 0; i < 4; i++)
#pragma unroll
        for (int j = 0; j < 4; j++) acc[i][j] = 0.f;

    const float* xb = xs + (ty * 4) * 129;
#pragma unroll 4
    for (int k = 0; k < INDIM; k++) {
        float xv[4], wv[4];
#pragma unroll
        for (int i = 0; i < 4; i++) xv[i] = xb[i * 129 + k];
#pragma unroll
        for (int j = 0; j < 4; j++) wv[j] = ws[(j * 32 + tx) * 129 + k];
#pragma unroll
        for (int i = 0; i < 4; i++)
#pragma unroll
            for (int j = 0; j < 4; j++) acc[i][j] += xv[i] * wv[j];
    }

#pragma unroll
    for (int j = 0; j < 4; j++) {
        int h = h0 + j * 32 + tx;
        float b = bi[h] + bh[h];
#pragma unroll
        for (int i = 0; i < 4; i++) {
            out[(size_t)(sb0 + ty * 4 + i) * HDIM + h] = acc[i][j] + b;
        }
    }
}

// ---------------------------------------------------------------------------
// Persistent recurrent kernel. 128 blocks = (bt 0..7) x (jt 0..15).
// Block (bt,jt) owns h[bt*8..+8][jt*32..+32] each step; Wh tile (32x512, 64KB)
// resident in SMEM for all 512 steps. h_{t-1} is read straight from L2 via
// __ldcg float2 (no SMEM staging). Compute uses packed fma.rn.f32x2 over
// k-pairs: warp tile 4b x 8j, lane = k-pair slice (k = d*64 + lane*2).
// Split-k-32 partials reduced with a 5-stage shuffle butterfly.
// ---------------------------------------------------------------------------
__global__ __launch_bounds__(RTHREADS, 1) void rnn_kernel(
    const float* __restrict__ Wh, float* out)
{
    extern __shared__ float sm[];
    float* sWh = sm;   // [32][512] 64KB, persistent

    const int tid  = threadIdx.x;
    const int bt   = blockIdx.x >> 4;
    const int jt   = blockIdx.x & 15;

    // load Wh tile once (rows jt*32 .. +31, contiguous)
    {
        const float4* src = (const float4*)(Wh + (size_t)jt * JT * HDIM);
        float4* dst = (float4*)sWh;
        for (int i = tid; i < JT * HDIM / 4; i += RTHREADS) dst[i] = src[i];
    }

    const int w    = tid >> 5;       // warp 0..7
    const int lane = tid & 31;       // k-pair slice lane
    const int tr   = w >> 2;         // 0..1 batch half   (rows tr*4..+3)
    const int tc   = w & 3;          // 0..3 j quarter    (cols tc*8..+7)

    // after butterfly, lane holds output index o = lane: b=o>>3, j=o&7
    const int ob = bt * BT + tr * 4 + (lane >> 3);
    const int oj = jt * JT + tc * 8 + (lane & 7);

    const u64* wb2 = (const u64*)sWh + (tc * 8) * (HDIM / 2) + lane;

    __syncthreads();

    for (int t = 1; t <= SEQ; t++) {
        const size_t oidx = (size_t)(t - 1) * (BATCH * HDIM) + (size_t)ob * HDIM + oj;
        // xi' = xi + bi + bh, precomputed; prefetch before the flag wait
        const float xiv = out[oidx];

        float sum = 0.f;
        if (t > 1) {
            // wait for the 16 producer blocks of our batch rows (step t-1)
            if (tid < GJ) {
                while (ld_acquire(&g_flag[bt][tid]) < t - 1) { }
            }
            __syncthreads();

            const float2* hb2 = (const float2*)&g_h[(t - 1) & 1][0][0]
                                + (bt * BT + tr * 4) * (HDIM / 2) + lane;

            u64 acc[4][8];
#pragma unroll
            for (int i = 0; i < 4; i++)
#pragma unroll
                for (int j = 0; j < 8; j++) acc[i][j] = 0ull;

#pragma unroll
            for (int d = 0; d < 8; d++) {     // 8 double-chunks of 64 k
                u64 hv[4], wv[8];
#pragma unroll
                for (int i = 0; i < 4; i++) {
                    float2 h2 = __ldcg(hb2 + i * (HDIM / 2) + d * 32);
                    hv[i] = *reinterpret_cast<u64*>(&h2);
                }
#pragma unroll
                for (int j = 0; j < 8; j++) wv[j] = wb2[j * (HDIM / 2) + d * 32];
#pragma unroll
                for (int i = 0; i < 4; i++)
#pragma unroll
                    for (int j = 0; j < 8; j++) acc[i][j] = fma2(hv[i], wv[j], acc[i][j]);
            }

            // collapse k-pairs, then 5-stage shuffle butterfly:
            // v[o] on lane s holds partial(output o, slice s);
            // after stage m, lane l holds outputs matching l on bits 0..m.
            float v[32];
#pragma unroll
            for (int i = 0; i < 4; i++)
#pragma unroll
                for (int j = 0; j < 8; j++) {
                    float2 a = *reinterpret_cast<float2*>(&acc[i][j]);
                    v[i * 8 + j] = a.x + a.y;
                }
#pragma unroll
            for (int m = 0; m < 5; m++) {
                const int mb = (lane >> m) & 1;
#pragma unroll
                for (int j2 = 0; j2 < (16 >> m); j2++) {
                    float send = v[2 * j2 + 1 - mb];
                    float recv = __shfl_xor_sync(0xffffffffu, send, 1 << m);
                    v[j2] = v[2 * j2 + mb] + recv;
                }
            }
            sum = v[0];
        }

        const float hval = tanhf(sum + xiv);

        out[oidx] = hval;                 // h_seq[t-1]
        g_h[t & 1][ob][oj] = hval;        // ping-pong state for step t+1
        if (t == SEQ) out[(size_t)SEQ * BATCH * HDIM + (size_t)ob * HDIM + oj] = hval;

        __syncthreads();                  // all block stores issued
        if (tid == 0) {
            __threadfence();              // single MEMBAR.GL, not 256
            st_release(&g_flag[bt][jt], t);
        }
    }
}

// ---------------------------------------------------------------------------
extern "C" void kernel_launch(void* const* d_in, const int* in_sizes, int n_in,
                              void* d_out, int out_size)
{
    const float* x  = (const float*)d_in[0];
    const float* Wi = (const float*)d_in[1];
    const float* bi = (const float*)d_in[2];
    const float* Wh = (const float*)d_in[3];
    const float* bh = (const float*)d_in[4];
    float* out = (float*)d_out;

    const int XI_SMEM  = (128 * 129 + 32 * 129) * 4;   // 82560 B
    const int RNN_SMEM = JT * HDIM * 4;                // 65536 B

    cudaFuncSetAttribute(xi_kernel,  cudaFuncAttributeMaxDynamicSharedMemorySize, XI_SMEM);
    cudaFuncSetAttribute(rnn_kernel, cudaFuncAttributeMaxDynamicSharedMemorySize, RNN_SMEM);

    reset_flags_kernel<<<1, 128>>>();
    xi_kernel<<<dim3(32768 / 32, HDIM / 128), 256, XI_SMEM>>>(x, Wi, bi, bh, out);
    rnn_kernel<<<GB * GJ, RTHREADS, RNN_SMEM>>>(Wh, out);
}